// round 1
// baseline (speedup 1.0000x reference)
#include <cuda_runtime.h>

// Problem dims
#define T_ 128
#define B_ 512
#define D_ 512
#define H_ 2048
#define C_ 18
#define M_ (T_ * B_)   // 65536 rows of the big GEMM

// Scratch (allocation-free rule: static __device__ globals)
__device__ float g_hall[(size_t)M_ * H_];   // 512 MB: h_all[t*B+b][h]
__device__ float g_z[B_ * H_];              // 4 MB: z at final timestep

// ---------------------------------------------------------------------------
// Phase 1: C[m][n] = sum_k A[m][k] * W[n][k] + bias[n]
// A = x_spikes [M, D]; W = W_in [H, D]; out -> g_hall
// Tile 64x64, K-chunk 16, 256 threads, 4x4 microtile. FFMA-bound by design.
// ---------------------------------------------------------------------------
__global__ void __launch_bounds__(256) gemm_kernel(const float* __restrict__ A,
                                                   const float* __restrict__ W,
                                                   const float* __restrict__ bias)
{
    const int K = D_;
    const int N = H_;

    // [buf][k][row] layout; row stride 68 floats (272B = 17*16B, float4-aligned,
    // pad breaks the worst bank-conflict patterns)
    __shared__ float As[2][16][68];
    __shared__ float Bs[2][16][68];

    const int tid = threadIdx.x;
    const int mBase = blockIdx.y * 64;
    const int nBase = blockIdx.x * 64;

    // global-load assignment: each thread loads one float4 per chunk per matrix
    const int lr = tid >> 2;    // 0..63  (row within tile)
    const int lk = tid & 3;     // 0..3   (k-quad within 16-chunk)

    const float* Aptr = A + (size_t)(mBase + lr) * K + 4 * lk;
    const float* Wptr = W + (size_t)(nBase + lr) * K + 4 * lk;

    // fragment assignment: 8 warps as 4(m) x 2(n); lanes as 4(m) x 8(n)
    const int warp = tid >> 5;
    const int lane = tid & 31;
    const int wm = warp >> 1;       // 0..3
    const int wn = warp & 1;        // 0..1
    const int lm = lane >> 3;       // 0..3
    const int ln = lane & 7;        // 0..7
    const int mo = wm * 16 + lm * 4;    // 0..60, multiple of 4
    const int no = wn * 32 + ln * 4;    // 0..60, multiple of 4

    float acc[4][4];
#pragma unroll
    for (int i = 0; i < 4; i++)
#pragma unroll
        for (int j = 0; j < 4; j++) acc[i][j] = 0.0f;

    // prime chunk 0
    float4 aR = *(const float4*)(Aptr);
    float4 bR = *(const float4*)(Wptr);
#pragma unroll
    for (int i = 0; i < 4; i++) {
        As[0][4 * lk + i][lr] = (&aR.x)[i];
        Bs[0][4 * lk + i][lr] = (&bR.x)[i];
    }
    __syncthreads();

    const int NKC = K / 16;   // 32 chunks
    for (int kc = 0; kc < NKC; kc++) {
        const int cur = kc & 1;
        // prefetch next chunk into registers (overlaps with FFMA block)
        if (kc + 1 < NKC) {
            aR = *(const float4*)(Aptr + (kc + 1) * 16);
            bR = *(const float4*)(Wptr + (kc + 1) * 16);
        }
#pragma unroll
        for (int k = 0; k < 16; k++) {
            float4 a = *(const float4*)&As[cur][k][mo];
            float4 b = *(const float4*)&Bs[cur][k][no];
            const float av[4] = {a.x, a.y, a.z, a.w};
            const float bv[4] = {b.x, b.y, b.z, b.w};
#pragma unroll
            for (int i = 0; i < 4; i++)
#pragma unroll
                for (int j = 0; j < 4; j++)
                    acc[i][j] = fmaf(av[i], bv[j], acc[i][j]);
        }
        if (kc + 1 < NKC) {
            const int nxt = 1 - cur;   // buffer last read at kc-1; safe to fill
#pragma unroll
            for (int i = 0; i < 4; i++) {
                As[nxt][4 * lk + i][lr] = (&aR.x)[i];
                Bs[nxt][4 * lk + i][lr] = (&bR.x)[i];
            }
            __syncthreads();
        }
    }

    // epilogue: add bias (folds b_in here so the scan is pure), float4 stores
    const int ncol = nBase + no;
    const float4 bb = *(const float4*)&bias[ncol];
#pragma unroll
    for (int i = 0; i < 4; i++) {
        float4 o;
        o.x = acc[i][0] + bb.x;
        o.y = acc[i][1] + bb.y;
        o.z = acc[i][2] + bb.z;
        o.w = acc[i][3] + bb.w;
        *(float4*)&g_hall[(size_t)(mBase + mo + i) * N + ncol] = o;
    }
}

// ---------------------------------------------------------------------------
// Phase 2: sequential LIF scan over t. Each thread owns 4 neurons (float4 over h).
// v = 0.9 v + h;  z = (v - 1 > 0);  v -= z.  Keep z of the final step.
// Fully coalesced: consecutive threads -> consecutive h.
// ---------------------------------------------------------------------------
__global__ void __launch_bounds__(256) scan_kernel()
{
    const int idx = blockIdx.x * blockDim.x + threadIdx.x;   // 0 .. B*H/4-1
    const int flat = idx * 4;                                // (b,h) flattened
    const float* p = g_hall + (size_t)flat;                  // row t: + t*B*H

    float v0 = 0.f, v1 = 0.f, v2 = 0.f, v3 = 0.f;
    float z0 = 0.f, z1 = 0.f, z2 = 0.f, z3 = 0.f;

#pragma unroll 4
    for (int t = 0; t < T_; t++) {
        const float4 hv = *(const float4*)(p + (size_t)t * ((size_t)B_ * H_));
        v0 = 0.9f * v0 + hv.x; z0 = (v0 > 1.0f) ? 1.0f : 0.0f; v0 -= z0;
        v1 = 0.9f * v1 + hv.y; z1 = (v1 > 1.0f) ? 1.0f : 0.0f; v1 -= z1;
        v2 = 0.9f * v2 + hv.z; z2 = (v2 > 1.0f) ? 1.0f : 0.0f; v2 -= z2;
        v3 = 0.9f * v3 + hv.w; z3 = (v3 > 1.0f) ? 1.0f : 0.0f; v3 -= z3;
    }
    *(float4*)&g_z[flat] = make_float4(z0, z1, z2, z3);
}

// ---------------------------------------------------------------------------
// Phase 3: logits[b][c] = sum_h z[b][h] * W_out[c][h] + b_out[c]
// One warp per (b, c): 9216 warps.
// ---------------------------------------------------------------------------
__global__ void __launch_bounds__(256) cls_kernel(const float* __restrict__ Wout,
                                                  const float* __restrict__ bout,
                                                  float* __restrict__ out)
{
    const int gw = (blockIdx.x * blockDim.x + threadIdx.x) >> 5;
    const int lane = threadIdx.x & 31;
    if (gw >= B_ * C_) return;
    const int b = gw / C_;
    const int c = gw % C_;

    const float* zp = g_z + (size_t)b * H_;
    const float* wp = Wout + (size_t)c * H_;

    float s = 0.0f;
#pragma unroll
    for (int h = lane * 4; h < H_; h += 32 * 4) {
        const float4 zz = *(const float4*)&zp[h];
        const float4 ww = *(const float4*)&wp[h];
        s = fmaf(zz.x, ww.x, s);
        s = fmaf(zz.y, ww.y, s);
        s = fmaf(zz.z, ww.z, s);
        s = fmaf(zz.w, ww.w, s);
    }
#pragma unroll
    for (int o = 16; o > 0; o >>= 1)
        s += __shfl_xor_sync(0xffffffffu, s, o);
    if (lane == 0) out[(size_t)b * C_ + c] = s + bout[c];
}

// ---------------------------------------------------------------------------
extern "C" void kernel_launch(void* const* d_in, const int* in_sizes, int n_in,
                              void* d_out, int out_size)
{
    const float* x     = (const float*)d_in[0];  // [T, B, D]
    const float* W_in  = (const float*)d_in[1];  // [H, D]
    const float* b_in  = (const float*)d_in[2];  // [H]
    const float* W_out = (const float*)d_in[3];  // [C, H]
    const float* b_out = (const float*)d_in[4];  // [C]
    float* out = (float*)d_out;                  // [B, C]

    dim3 gGemm(H_ / 64, M_ / 64);                // 32 x 1024 CTAs
    gemm_kernel<<<gGemm, 256>>>(x, W_in, b_in);

    scan_kernel<<<(B_ * H_ / 4) / 256, 256>>>(); // 1024 CTAs

    cls_kernel<<<(B_ * C_ * 32) / 256, 256>>>(W_out, b_out, out); // 1152 CTAs
}

// round 6
// speedup vs baseline: 1.3524x; 1.3524x over previous
#include <cuda_runtime.h>
#include <cstdint>

#define T_ 128
#define B_ 512
#define D_ 512
#define H_ 2048
#define C_ 18
#define M_ (T_ * B_)   // 65536

// ---------------- device scratch (allocation-free rule) ----------------
__device__ float g_hall[(size_t)M_ * H_];   // 512 MB
__device__ float g_z[B_ * H_];

// ---------------------------------------------------------------------------
// Phase 1: h[m][n] = sum_k x[m][k] * W[n][k] + bias[n]
// CTA tile 128x128, K-chunk 16, 256 threads, 8x8 microtile.
// Numerics: per-thread k-sequential fp32 FMA (same class as round-1 PASS).
// SMEM [k][row] with stride 132 (+4 pad); reg-prefetch double buffering.
// ---------------------------------------------------------------------------
#define KC 16
#define SSTR 132

__global__ void __launch_bounds__(256, 2) gemm_kernel(const float* __restrict__ A,
                                                      const float* __restrict__ W,
                                                      const float* __restrict__ bias)
{
    __shared__ float As[2][KC][SSTR];
    __shared__ float Bs[2][KC][SSTR];

    const int tid = threadIdx.x;
    const int m0 = (int)blockIdx.y * 128;
    const int n0 = (int)blockIdx.x * 128;

    // global-load mapping: thread covers rows r0 and r0+64, k-quad kq
    const int r0 = tid >> 2;            // 0..63
    const int kq = tid & 3;             // 0..3 -> k offset 4*kq
    const float* Ap = A + (size_t)(m0 + r0) * D_ + 4 * kq;
    const float* Wp = W + (size_t)(n0 + r0) * D_ + 4 * kq;

    // fragment mapping: 8 warps as 4(m) x 2(n); lanes as 4(m) x 8(n)
    const int wid = tid >> 5;
    const int lane = tid & 31;
    const int wm = wid >> 1;            // 0..3 -> 32 m-rows each
    const int wn = wid & 1;             // 0..1 -> 64 n-cols each
    const int mo = wm * 32 + (lane & 3) * 8;    // 0..120, mult of 8
    const int no = wn * 64 + (lane >> 2) * 8;   // 0..120, mult of 8

    float acc[8][8];
#pragma unroll
    for (int i = 0; i < 8; i++)
#pragma unroll
        for (int j = 0; j < 8; j++) acc[i][j] = 0.0f;

    // prime stage 0
    float4 a0 = *(const float4*)(Ap);
    float4 a1 = *(const float4*)(Ap + 64 * D_);
    float4 b0 = *(const float4*)(Wp);
    float4 b1 = *(const float4*)(Wp + 64 * D_);
#pragma unroll
    for (int j = 0; j < 4; j++) {
        As[0][4 * kq + j][r0]      = (&a0.x)[j];
        As[0][4 * kq + j][r0 + 64] = (&a1.x)[j];
        Bs[0][4 * kq + j][r0]      = (&b0.x)[j];
        Bs[0][4 * kq + j][r0 + 64] = (&b1.x)[j];
    }
    __syncthreads();

    const int NST = D_ / KC;   // 32
    for (int s = 0; s < NST; s++) {
        const int cur = s & 1;
        if (s + 1 < NST) {   // prefetch next stage into registers
            const int ko = (s + 1) * KC;
            a0 = *(const float4*)(Ap + ko);
            a1 = *(const float4*)(Ap + 64 * D_ + ko);
            b0 = *(const float4*)(Wp + ko);
            b1 = *(const float4*)(Wp + 64 * D_ + ko);
        }
#pragma unroll
        for (int k = 0; k < KC; k++) {
            float a[8], b[8];
            *(float4*)(a)     = *(const float4*)&As[cur][k][mo];
            *(float4*)(a + 4) = *(const float4*)&As[cur][k][mo + 4];
            *(float4*)(b)     = *(const float4*)&Bs[cur][k][no];
            *(float4*)(b + 4) = *(const float4*)&Bs[cur][k][no + 4];
#pragma unroll
            for (int i = 0; i < 8; i++)
#pragma unroll
                for (int j = 0; j < 8; j++)
                    acc[i][j] = fmaf(a[i], b[j], acc[i][j]);
        }
        if (s + 1 < NST) {
            const int nxt = 1 - cur;   // holds stage s-1 data, already consumed
#pragma unroll
            for (int j = 0; j < 4; j++) {
                As[nxt][4 * kq + j][r0]      = (&a0.x)[j];
                As[nxt][4 * kq + j][r0 + 64] = (&a1.x)[j];
                Bs[nxt][4 * kq + j][r0]      = (&b0.x)[j];
                Bs[nxt][4 * kq + j][r0 + 64] = (&b1.x)[j];
            }
            __syncthreads();
        }
    }

    // epilogue: h = acc + bias
    const int col = n0 + no;
    const float4 bb0 = *(const float4*)&bias[col];
    const float4 bb1 = *(const float4*)&bias[col + 4];
#pragma unroll
    for (int i = 0; i < 8; i++) {
        float* dst = g_hall + (size_t)(m0 + mo + i) * H_ + col;
        float4 o0, o1;
        o0.x = acc[i][0] + bb0.x; o0.y = acc[i][1] + bb0.y;
        o0.z = acc[i][2] + bb0.z; o0.w = acc[i][3] + bb0.w;
        o1.x = acc[i][4] + bb1.x; o1.y = acc[i][5] + bb1.y;
        o1.z = acc[i][6] + bb1.z; o1.w = acc[i][7] + bb1.w;
        *(float4*)(dst)     = o0;
        *(float4*)(dst + 4) = o1;
    }
}

// ---------------- Phase 2: sequential LIF scan ----------------
__global__ void __launch_bounds__(256) scan_kernel()
{
    const int idx = blockIdx.x * blockDim.x + threadIdx.x;
    const int flat = idx * 4;
    const float* p = g_hall + (size_t)flat;

    float v0 = 0.f, v1 = 0.f, v2 = 0.f, v3 = 0.f;
    float z0 = 0.f, z1 = 0.f, z2 = 0.f, z3 = 0.f;

#pragma unroll 4
    for (int t = 0; t < T_; t++) {
        const float4 hv = *(const float4*)(p + (size_t)t * ((size_t)B_ * H_));
        v0 = 0.9f * v0 + hv.x; z0 = (v0 > 1.0f) ? 1.0f : 0.0f; v0 -= z0;
        v1 = 0.9f * v1 + hv.y; z1 = (v1 > 1.0f) ? 1.0f : 0.0f; v1 -= z1;
        v2 = 0.9f * v2 + hv.z; z2 = (v2 > 1.0f) ? 1.0f : 0.0f; v2 -= z2;
        v3 = 0.9f * v3 + hv.w; z3 = (v3 > 1.0f) ? 1.0f : 0.0f; v3 -= z3;
    }
    *(float4*)&g_z[flat] = make_float4(z0, z1, z2, z3);
}

// ---------------- Phase 3: classifier ----------------
__global__ void __launch_bounds__(256) cls_kernel(const float* __restrict__ Wout,
                                                  const float* __restrict__ bout,
                                                  float* __restrict__ out)
{
    const int gw = (blockIdx.x * blockDim.x + threadIdx.x) >> 5;
    const int lane = threadIdx.x & 31;
    if (gw >= B_ * C_) return;
    const int b = gw / C_;
    const int c = gw % C_;

    const float* zp = g_z + (size_t)b * H_;
    const float* wp = Wout + (size_t)c * H_;

    float s = 0.0f;
#pragma unroll
    for (int h = lane * 4; h < H_; h += 32 * 4) {
        const float4 zz = *(const float4*)&zp[h];
        const float4 ww = *(const float4*)&wp[h];
        s = fmaf(zz.x, ww.x, s);
        s = fmaf(zz.y, ww.y, s);
        s = fmaf(zz.z, ww.z, s);
        s = fmaf(zz.w, ww.w, s);
    }
#pragma unroll
    for (int o = 16; o > 0; o >>= 1)
        s += __shfl_xor_sync(0xffffffffu, s, o);
    if (lane == 0) out[(size_t)b * C_ + c] = s + bout[c];
}

// ---------------------------------------------------------------------------
extern "C" void kernel_launch(void* const* d_in, const int* in_sizes, int n_in,
                              void* d_out, int out_size)
{
    const float* x     = (const float*)d_in[0];  // [T, B, D]
    const float* W_in  = (const float*)d_in[1];  // [H, D]
    const float* b_in  = (const float*)d_in[2];  // [H]
    const float* W_out = (const float*)d_in[3];  // [C, H]
    const float* b_out = (const float*)d_in[4];  // [C]
    float* out = (float*)d_out;                  // [B, C]

    dim3 g(H_ / 128, M_ / 128);                  // 16 x 512 CTAs
    gemm_kernel<<<g, 256>>>(x, W_in, b_in);

    scan_kernel<<<(B_ * H_ / 4) / 256, 256>>>(); // 1024 CTAs

    cls_kernel<<<(B_ * C_ * 32) / 256, 256>>>(W_out, b_out, out); // 1152 CTAs
}

// round 7
// speedup vs baseline: 1.3700x; 1.0130x over previous
#include <cuda_runtime.h>
#include <cstdint>

#define T_ 128
#define B_ 512
#define D_ 512
#define H_ 2048
#define C_ 18
#define M_ (T_ * B_)   // 65536

// ---------------- device scratch (allocation-free rule) ----------------
__device__ float g_hall[(size_t)M_ * H_];   // 512 MB
__device__ float g_z[B_ * H_];

// ---------------------------------------------------------------------------
// Phase 1: h[m][n] = sum_k x[m][k] * W[n][k] + bias[n]
// CTA tile 128x128, K-chunk 16, 256 threads, 8x8 microtile, 2 CTAs/SM.
// Round-7 changes vs round-6 (arithmetic order identical):
//   - fragment double-buffering (LDS for k+1 issued before FFMA block of k)
//   - stage loop unrolled x2 so smem buffer indices are compile-time
//   - STS for next stage placed mid-loop (k==9), after LDG data arrival
//   - streaming stores (__stwt) for g_hall
// ---------------------------------------------------------------------------
#define KC 16
#define SSTR 132

__global__ void __launch_bounds__(256, 2) gemm_kernel(const float* __restrict__ A,
                                                      const float* __restrict__ W,
                                                      const float* __restrict__ bias)
{
    __shared__ float As[2][KC][SSTR];
    __shared__ float Bs[2][KC][SSTR];

    const int tid = threadIdx.x;
    const int m0 = (int)blockIdx.y * 128;
    const int n0 = (int)blockIdx.x * 128;

    // global-load mapping: thread covers rows r0 and r0+64, k-quad kq
    const int r0 = tid >> 2;            // 0..63
    const int kq = tid & 3;             // 0..3 -> k offset 4*kq
    const float* Ap = A + (size_t)(m0 + r0) * D_ + 4 * kq;
    const float* Wp = W + (size_t)(n0 + r0) * D_ + 4 * kq;

    // fragment mapping: 8 warps as 4(m) x 2(n); lanes as 4(m) x 8(n)
    const int wid = tid >> 5;
    const int lane = tid & 31;
    const int mo = (wid >> 1) * 32 + (lane & 3) * 8;    // 0..120, mult of 8
    const int no = (wid & 1) * 64 + (lane >> 2) * 8;    // 0..120, mult of 8

    float acc[8][8];
#pragma unroll
    for (int i = 0; i < 8; i++)
#pragma unroll
        for (int j = 0; j < 8; j++) acc[i][j] = 0.0f;

    // prime stage 0
    {
        float4 a0 = *(const float4*)(Ap);
        float4 a1 = *(const float4*)(Ap + 64 * D_);
        float4 b0 = *(const float4*)(Wp);
        float4 b1 = *(const float4*)(Wp + 64 * D_);
#pragma unroll
        for (int j = 0; j < 4; j++) {
            As[0][4 * kq + j][r0]      = (&a0.x)[j];
            As[0][4 * kq + j][r0 + 64] = (&a1.x)[j];
            Bs[0][4 * kq + j][r0]      = (&b0.x)[j];
            Bs[0][4 * kq + j][r0 + 64] = (&b1.x)[j];
        }
    }
    __syncthreads();

    float af[2][8], bf[2][8];

#define LDFRAG(buf, CUR, k) do { \
        *(float4*)(af[buf])     = *(const float4*)&As[CUR][k][mo]; \
        *(float4*)(af[buf] + 4) = *(const float4*)&As[CUR][k][mo + 4]; \
        *(float4*)(bf[buf])     = *(const float4*)&Bs[CUR][k][no]; \
        *(float4*)(bf[buf] + 4) = *(const float4*)&Bs[CUR][k][no + 4]; \
    } while (0)

#define STAGE(CUR, s) do { \
        const bool more = (s) + 1 < NST; \
        float4 a0, a1, b0, b1; \
        if (more) { \
            const int ko = ((s) + 1) * KC; \
            a0 = *(const float4*)(Ap + ko); \
            a1 = *(const float4*)(Ap + 64 * D_ + ko); \
            b0 = *(const float4*)(Wp + ko); \
            b1 = *(const float4*)(Wp + 64 * D_ + ko); \
        } \
        LDFRAG(0, CUR, 0); \
        _Pragma("unroll") \
        for (int k = 0; k < KC; k++) { \
            if (k + 1 < KC) LDFRAG((k + 1) & 1, CUR, k + 1); \
            if (k == 9 && more) { \
                _Pragma("unroll") \
                for (int j = 0; j < 4; j++) { \
                    As[CUR ^ 1][4 * kq + j][r0]      = (&a0.x)[j]; \
                    As[CUR ^ 1][4 * kq + j][r0 + 64] = (&a1.x)[j]; \
                    Bs[CUR ^ 1][4 * kq + j][r0]      = (&b0.x)[j]; \
                    Bs[CUR ^ 1][4 * kq + j][r0 + 64] = (&b1.x)[j]; \
                } \
            } \
            { \
                const int fb = k & 1; \
                _Pragma("unroll") \
                for (int i = 0; i < 8; i++) \
                    _Pragma("unroll") \
                    for (int j = 0; j < 8; j++) \
                        acc[i][j] = fmaf(af[fb][i], bf[fb][j], acc[i][j]); \
            } \
        } \
        if (more) __syncthreads(); \
    } while (0)

    const int NST = D_ / KC;   // 32 (even)
    for (int s = 0; s < NST; s += 2) {
        STAGE(0, s);
        STAGE(1, s + 1);
    }

#undef STAGE
#undef LDFRAG

    // epilogue: h = acc + bias (streaming stores — scan can't reuse L2 anyway)
    const int col = n0 + no;
    const float4 bb0 = *(const float4*)&bias[col];
    const float4 bb1 = *(const float4*)&bias[col + 4];
#pragma unroll
    for (int i = 0; i < 8; i++) {
        float* dst = g_hall + (size_t)(m0 + mo + i) * H_ + col;
        float4 o0, o1;
        o0.x = acc[i][0] + bb0.x; o0.y = acc[i][1] + bb0.y;
        o0.z = acc[i][2] + bb0.z; o0.w = acc[i][3] + bb0.w;
        o1.x = acc[i][4] + bb1.x; o1.y = acc[i][5] + bb1.y;
        o1.z = acc[i][6] + bb1.z; o1.w = acc[i][7] + bb1.w;
        __stwt((float4*)(dst), o0);
        __stwt((float4*)(dst + 4), o1);
    }
}

// ---------------- Phase 2: sequential LIF scan ----------------
__global__ void __launch_bounds__(256) scan_kernel()
{
    const int idx = blockIdx.x * blockDim.x + threadIdx.x;
    const int flat = idx * 4;
    const float* p = g_hall + (size_t)flat;

    float v0 = 0.f, v1 = 0.f, v2 = 0.f, v3 = 0.f;
    float z0 = 0.f, z1 = 0.f, z2 = 0.f, z3 = 0.f;

#pragma unroll 4
    for (int t = 0; t < T_; t++) {
        const float4 hv = *(const float4*)(p + (size_t)t * ((size_t)B_ * H_));
        v0 = 0.9f * v0 + hv.x; z0 = (v0 > 1.0f) ? 1.0f : 0.0f; v0 -= z0;
        v1 = 0.9f * v1 + hv.y; z1 = (v1 > 1.0f) ? 1.0f : 0.0f; v1 -= z1;
        v2 = 0.9f * v2 + hv.z; z2 = (v2 > 1.0f) ? 1.0f : 0.0f; v2 -= z2;
        v3 = 0.9f * v3 + hv.w; z3 = (v3 > 1.0f) ? 1.0f : 0.0f; v3 -= z3;
    }
    *(float4*)&g_z[flat] = make_float4(z0, z1, z2, z3);
}

// ---------------- Phase 3: classifier ----------------
__global__ void __launch_bounds__(256) cls_kernel(const float* __restrict__ Wout,
                                                  const float* __restrict__ bout,
                                                  float* __restrict__ out)
{
    const int gw = (blockIdx.x * blockDim.x + threadIdx.x) >> 5;
    const int lane = threadIdx.x & 31;
    if (gw >= B_ * C_) return;
    const int b = gw / C_;
    const int c = gw % C_;

    const float* zp = g_z + (size_t)b * H_;
    const float* wp = Wout + (size_t)c * H_;

    float s = 0.0f;
#pragma unroll
    for (int h = lane * 4; h < H_; h += 32 * 4) {
        const float4 zz = *(const float4*)&zp[h];
        const float4 ww = *(const float4*)&wp[h];
        s = fmaf(zz.x, ww.x, s);
        s = fmaf(zz.y, ww.y, s);
        s = fmaf(zz.z, ww.z, s);
        s = fmaf(zz.w, ww.w, s);
    }
#pragma unroll
    for (int o = 16; o > 0; o >>= 1)
        s += __shfl_xor_sync(0xffffffffu, s, o);
    if (lane == 0) out[(size_t)b * C_ + c] = s + bout[c];
}

// ---------------------------------------------------------------------------
extern "C" void kernel_launch(void* const* d_in, const int* in_sizes, int n_in,
                              void* d_out, int out_size)
{
    const float* x     = (const float*)d_in[0];  // [T, B, D]
    const float* W_in  = (const float*)d_in[1];  // [H, D]
    const float* b_in  = (const float*)d_in[2];  // [H]
    const float* W_out = (const float*)d_in[3];  // [C, H]
    const float* b_out = (const float*)d_in[4];  // [C]
    float* out = (float*)d_out;                  // [B, C]

    dim3 g(H_ / 128, M_ / 128);                  // 16 x 512 CTAs
    gemm_kernel<<<g, 256>>>(x, W_in, b_in);

    scan_kernel<<<(B_ * H_ / 4) / 256, 256>>>(); // 1024 CTAs

    cls_kernel<<<(B_ * C_ * 32) / 256, 256>>>(W_out, b_out, out); // 1152 CTAs
}

// round 8
// speedup vs baseline: 1.4956x; 1.0917x over previous
#include <cuda_runtime.h>
#include <cstdint>

#define T_ 128
#define B_ 512
#define D_ 512
#define H_ 2048
#define C_ 18
#define M_ (T_ * B_)   // 65536

// ---------------- device scratch (allocation-free rule) ----------------
__device__ float g_At[(size_t)D_ * M_];     // 134 MB: x transposed [k][m]
__device__ float g_Wt[(size_t)D_ * H_];     // 4 MB:   W_in transposed [k][n]
__device__ float g_hall[(size_t)M_ * H_];   // 512 MB
__device__ float g_z[B_ * H_];

static __device__ __forceinline__ uint32_t s2u(const void* p) {
    uint32_t a;
    asm("{ .reg .u64 t; cvta.to.shared.u64 t, %1; cvt.u32.u64 %0, t; }" : "=r"(a) : "l"(p));
    return a;
}

// ---------------------------------------------------------------------------
// Phase 0: tiled transpose  out[c][r] = in[r][c]
// ---------------------------------------------------------------------------
__global__ void __launch_bounds__(256) transpose_kernel(const float* __restrict__ in,
                                                        float* __restrict__ out,
                                                        int R, int Ccol)
{
    __shared__ float t[32][33];
    const int bx = blockIdx.x * 32;   // col base
    const int by = blockIdx.y * 32;   // row base
    const int x = threadIdx.x;
    const int y = threadIdx.y;
#pragma unroll
    for (int i = 0; i < 32; i += 8)
        t[y + i][x] = in[(size_t)(by + y + i) * Ccol + bx + x];
    __syncthreads();
#pragma unroll
    for (int i = 0; i < 32; i += 8)
        out[(size_t)(bx + y + i) * R + by + x] = t[x][y + i];
}

// ---------------------------------------------------------------------------
// Phase 1: h[m][n] = sum_k At[k][m] * Wt[k][n] + bias[n]
// CTA tile 128x128, 256 threads, 8x8 microtile, KC=32, 3-stage cp.async ring,
// ONE __syncthreads per stage. Per-thread k-order = 0..511 sequential
// (bit-identical numerics to rounds 6/7).
// ---------------------------------------------------------------------------
#define KC 32
#define BUF_FLOATS (2 * KC * 128)            // As + Bs per buffer = 8192 floats
#define SMEM_BYTES (3 * BUF_FLOATS * 4)      // 96 KB

__global__ void __launch_bounds__(256, 2) gemm_kernel(const float* __restrict__ bias)
{
    extern __shared__ float sm[];
    const uint32_t sb = s2u(sm);
    const int tid = threadIdx.x;
    const int m0 = (int)blockIdx.y * 128;
    const int n0 = (int)blockIdx.x * 128;

    // fragment mapping: 8 warps as 4(m) x 2(n); lanes as 4(m) x 8(n)
    const int wid = tid >> 5;
    const int lane = tid & 31;
    const int mo = (wid >> 1) * 32 + (lane & 3) * 8;    // 0..120, mult of 8
    const int no = (wid & 1) * 64 + (lane >> 2) * 8;    // 0..120, mult of 8

    // cp.async chunk mapping: 4 chunks/thread/matrix; chunk c -> k=c>>5, m-offset=(c&31)*4
    const float* At0 = g_At + m0;        // + k*M_ + cm
    const float* Wt0 = g_Wt + n0;        // + k*H_ + cm

    auto load_stage = [&](int buf, int kBase) {
        const uint32_t bufb = sb + (uint32_t)buf * (BUF_FLOATS * 4);
        const float* sa = At0 + (size_t)kBase * M_;
        const float* sbp = Wt0 + (size_t)kBase * H_;
#pragma unroll
        for (int i = 0; i < 4; i++) {
            const int c = i * 256 + tid;
            const int k = c >> 5;
            const int cm = (c & 31) * 4;
            const uint32_t da = bufb + (uint32_t)(k * 128 + cm) * 4;
            asm volatile("cp.async.cg.shared.global [%0], [%1], 16;"
                         :: "r"(da), "l"(sa + (size_t)k * M_ + cm));
        }
#pragma unroll
        for (int i = 0; i < 4; i++) {
            const int c = i * 256 + tid;
            const int k = c >> 5;
            const int cm = (c & 31) * 4;
            const uint32_t db = bufb + (uint32_t)(KC * 128 + k * 128 + cm) * 4;
            asm volatile("cp.async.cg.shared.global [%0], [%1], 16;"
                         :: "r"(db), "l"(sbp + (size_t)k * H_ + cm));
        }
        asm volatile("cp.async.commit_group;" ::: "memory");
    };

    float acc[8][8];
#pragma unroll
    for (int i = 0; i < 8; i++)
#pragma unroll
        for (int j = 0; j < 8; j++) acc[i][j] = 0.0f;

    load_stage(0, 0);
    load_stage(1, KC);

    float af[2][8], bf[2][8];
    const int NST = D_ / KC;   // 16

    for (int s = 0; s < NST; s++) {
        // per-thread wait for own group of stage s, THEN barrier, THEN consume
        if (s == NST - 1)
            asm volatile("cp.async.wait_group 0;" ::: "memory");
        else
            asm volatile("cp.async.wait_group 1;" ::: "memory");
        __syncthreads();
        // buffer of stage s-1 is now free for stage s+2
        if (s + 2 < NST) load_stage((s + 2) % 3, (s + 2) * KC);

        const float* Ab = sm + (size_t)(s % 3) * BUF_FLOATS;
        const float* Bb = Ab + KC * 128;

#define LDFRAG(fb, k) do { \
        *(float4*)(af[fb])     = *(const float4*)&Ab[(k) * 128 + mo]; \
        *(float4*)(af[fb] + 4) = *(const float4*)&Ab[(k) * 128 + mo + 4]; \
        *(float4*)(bf[fb])     = *(const float4*)&Bb[(k) * 128 + no]; \
        *(float4*)(bf[fb] + 4) = *(const float4*)&Bb[(k) * 128 + no + 4]; \
    } while (0)

        LDFRAG(0, 0);
#pragma unroll
        for (int k = 0; k < KC; k++) {
            if (k + 1 < KC) LDFRAG((k + 1) & 1, k + 1);
            const int fb = k & 1;
#pragma unroll
            for (int i = 0; i < 8; i++)
#pragma unroll
                for (int j = 0; j < 8; j++)
                    acc[i][j] = fmaf(af[fb][i], bf[fb][j], acc[i][j]);
        }
#undef LDFRAG
    }

    // epilogue: h = acc + bias (streaming stores)
    const int col = n0 + no;
    const float4 bb0 = *(const float4*)&bias[col];
    const float4 bb1 = *(const float4*)&bias[col + 4];
#pragma unroll
    for (int i = 0; i < 8; i++) {
        float* dst = g_hall + (size_t)(m0 + mo + i) * H_ + col;
        float4 o0, o1;
        o0.x = acc[i][0] + bb0.x; o0.y = acc[i][1] + bb0.y;
        o0.z = acc[i][2] + bb0.z; o0.w = acc[i][3] + bb0.w;
        o1.x = acc[i][4] + bb1.x; o1.y = acc[i][5] + bb1.y;
        o1.z = acc[i][6] + bb1.z; o1.w = acc[i][7] + bb1.w;
        __stwt((float4*)(dst), o0);
        __stwt((float4*)(dst + 4), o1);
    }
}

// ---------------- Phase 2: sequential LIF scan ----------------
__global__ void __launch_bounds__(256) scan_kernel()
{
    const int idx = blockIdx.x * blockDim.x + threadIdx.x;
    const int flat = idx * 4;
    const float* p = g_hall + (size_t)flat;

    float v0 = 0.f, v1 = 0.f, v2 = 0.f, v3 = 0.f;
    float z0 = 0.f, z1 = 0.f, z2 = 0.f, z3 = 0.f;

#pragma unroll 4
    for (int t = 0; t < T_; t++) {
        const float4 hv = __ldcs((const float4*)(p + (size_t)t * ((size_t)B_ * H_)));
        v0 = 0.9f * v0 + hv.x; z0 = (v0 > 1.0f) ? 1.0f : 0.0f; v0 -= z0;
        v1 = 0.9f * v1 + hv.y; z1 = (v1 > 1.0f) ? 1.0f : 0.0f; v1 -= z1;
        v2 = 0.9f * v2 + hv.z; z2 = (v2 > 1.0f) ? 1.0f : 0.0f; v2 -= z2;
        v3 = 0.9f * v3 + hv.w; z3 = (v3 > 1.0f) ? 1.0f : 0.0f; v3 -= z3;
    }
    *(float4*)&g_z[flat] = make_float4(z0, z1, z2, z3);
}

// ---------------- Phase 3: classifier ----------------
__global__ void __launch_bounds__(256) cls_kernel(const float* __restrict__ Wout,
                                                  const float* __restrict__ bout,
                                                  float* __restrict__ out)
{
    const int gw = (blockIdx.x * blockDim.x + threadIdx.x) >> 5;
    const int lane = threadIdx.x & 31;
    if (gw >= B_ * C_) return;
    const int b = gw / C_;
    const int c = gw % C_;

    const float* zp = g_z + (size_t)b * H_;
    const float* wp = Wout + (size_t)c * H_;

    float s = 0.0f;
#pragma unroll
    for (int h = lane * 4; h < H_; h += 32 * 4) {
        const float4 zz = *(const float4*)&zp[h];
        const float4 ww = *(const float4*)&wp[h];
        s = fmaf(zz.x, ww.x, s);
        s = fmaf(zz.y, ww.y, s);
        s = fmaf(zz.z, ww.z, s);
        s = fmaf(zz.w, ww.w, s);
    }
#pragma unroll
    for (int o = 16; o > 0; o >>= 1)
        s += __shfl_xor_sync(0xffffffffu, s, o);
    if (lane == 0) out[(size_t)b * C_ + c] = s + bout[c];
}

// ---------------------------------------------------------------------------
extern "C" void kernel_launch(void* const* d_in, const int* in_sizes, int n_in,
                              void* d_out, int out_size)
{
    const float* x     = (const float*)d_in[0];  // [T, B, D] = [M, D]
    const float* W_in  = (const float*)d_in[1];  // [H, D]
    const float* b_in  = (const float*)d_in[2];  // [H]
    const float* W_out = (const float*)d_in[3];  // [C, H]
    const float* b_out = (const float*)d_in[4];  // [C]
    float* out = (float*)d_out;                  // [B, C]

    cudaFuncSetAttribute(gemm_kernel, cudaFuncAttributeMaxDynamicSharedMemorySize, SMEM_BYTES);

    void *pAt, *pWt;
    cudaGetSymbolAddress(&pAt, g_At);
    cudaGetSymbolAddress(&pWt, g_Wt);

    dim3 tb(32, 8);
    transpose_kernel<<<dim3(D_ / 32, M_ / 32), tb>>>(x, (float*)pAt, M_, D_);
    transpose_kernel<<<dim3(D_ / 32, H_ / 32), tb>>>(W_in, (float*)pWt, H_, D_);

    dim3 g(H_ / 128, M_ / 128);                  // 16 x 512 CTAs
    gemm_kernel<<<g, 256, SMEM_BYTES>>>(b_in);

    scan_kernel<<<(B_ * H_ / 4) / 256, 256>>>(); // 1024 CTAs

    cls_kernel<<<(B_ * C_ * 32) / 256, 256>>>(W_out, b_out, out); // 1152 CTAs
}

// round 9
// speedup vs baseline: 1.6061x; 1.0739x over previous
#include <cuda_runtime.h>
#include <cstdint>

#define T_ 128
#define B_ 512
#define D_ 512
#define H_ 2048
#define C_ 18
#define M_ (T_ * B_)   // 65536

// ---------------- device scratch (allocation-free rule) ----------------
__device__ float g_At[(size_t)D_ * M_];     // 134 MB: x transposed [k][m]
__device__ float g_Wt[(size_t)D_ * H_];     // 4 MB:   W_in transposed [k][n]
__device__ float g_hall[(size_t)M_ * H_];   // 512 MB
__device__ float g_z[B_ * H_];

static __device__ __forceinline__ uint32_t s2u(const void* p) {
    uint32_t a;
    asm("{ .reg .u64 t; cvta.to.shared.u64 t, %1; cvt.u32.u64 %0, t; }" : "=r"(a) : "l"(p));
    return a;
}

// packed f32x2 helpers (two independent IEEE fp32 ops -> bit-identical to fmaf)
#define PACK2(d, s)   asm("mov.b64 %0, {%1, %1};" : "=l"(d) : "f"(s))
#define FMA2(acc, a, b) \
    asm("fma.rn.f32x2 %0, %1, %2, %0;" : "+l"(acc) : "l"(a), "l"(b))
#define UNPK2(lo, hi, s) asm("mov.b64 {%0, %1}, %2;" : "=f"(lo), "=f"(hi) : "l"(s))

// ---------------------------------------------------------------------------
// Phase 0: tiled transpose  out[c][r] = in[r][c]
// ---------------------------------------------------------------------------
__global__ void __launch_bounds__(256) transpose_kernel(const float* __restrict__ in,
                                                        float* __restrict__ out,
                                                        int R, int Ccol)
{
    __shared__ float t[32][33];
    const int bx = blockIdx.x * 32;
    const int by = blockIdx.y * 32;
    const int x = threadIdx.x;
    const int y = threadIdx.y;
#pragma unroll
    for (int i = 0; i < 32; i += 8)
        t[y + i][x] = in[(size_t)(by + y + i) * Ccol + bx + x];
    __syncthreads();
#pragma unroll
    for (int i = 0; i < 32; i += 8)
        out[(size_t)(bx + y + i) * R + by + x] = t[x][y + i];
}

// ---------------------------------------------------------------------------
// Phase 1: h[m][n] = sum_k At[k][m] * Wt[k][n] + bias[n]
// CTA tile 128x128, 256 threads, 8x8 microtile, KC=32, 3-stage cp.async ring.
// Inner product uses fma.rn.f32x2 (FFMA2): acc packed along n in u64 pairs,
// per-component arithmetic identical to scalar fmaf in k-order 0..511.
// ---------------------------------------------------------------------------
#define KC 32
#define BUF_FLOATS (2 * KC * 128)            // 8192 floats / buffer
#define SMEM_BYTES (3 * BUF_FLOATS * 4)      // 96 KB

__global__ void __launch_bounds__(256, 2) gemm_kernel(const float* __restrict__ bias)
{
    extern __shared__ float sm[];
    const uint32_t sb = s2u(sm);
    const int tid = threadIdx.x;
    const int m0 = (int)blockIdx.y * 128;
    const int n0 = (int)blockIdx.x * 128;

    const int wid = tid >> 5;
    const int lane = tid & 31;
    const int mo = (wid >> 1) * 32 + (lane & 3) * 8;    // 0..120
    const int no = (wid & 1) * 64 + (lane >> 2) * 8;    // 0..120

    const float* At0 = g_At + m0;
    const float* Wt0 = g_Wt + n0;

    auto load_stage = [&](int buf, int kBase) {
        const uint32_t bufb = sb + (uint32_t)buf * (BUF_FLOATS * 4);
        const float* sa = At0 + (size_t)kBase * M_;
        const float* sbp = Wt0 + (size_t)kBase * H_;
#pragma unroll
        for (int i = 0; i < 4; i++) {
            const int c = i * 256 + tid;
            const int k = c >> 5;
            const int cm = (c & 31) * 4;
            const uint32_t da = bufb + (uint32_t)(k * 128 + cm) * 4;
            asm volatile("cp.async.cg.shared.global [%0], [%1], 16;"
                         :: "r"(da), "l"(sa + (size_t)k * M_ + cm));
        }
#pragma unroll
        for (int i = 0; i < 4; i++) {
            const int c = i * 256 + tid;
            const int k = c >> 5;
            const int cm = (c & 31) * 4;
            const uint32_t db = bufb + (uint32_t)(KC * 128 + k * 128 + cm) * 4;
            asm volatile("cp.async.cg.shared.global [%0], [%1], 16;"
                         :: "r"(db), "l"(sbp + (size_t)k * H_ + cm));
        }
        asm volatile("cp.async.commit_group;" ::: "memory");
    };

    // acc[i][jj]: row i (8), packed n-pair jj (4) -> 64 fp32 values
    unsigned long long acc[8][4];
#pragma unroll
    for (int i = 0; i < 8; i++)
#pragma unroll
        for (int j = 0; j < 4; j++) acc[i][j] = 0ull;

    load_stage(0, 0);
    load_stage(1, KC);

    const int NST = D_ / KC;   // 16

    for (int s = 0; s < NST; s++) {
        if (s == NST - 1)
            asm volatile("cp.async.wait_group 0;" ::: "memory");
        else
            asm volatile("cp.async.wait_group 1;" ::: "memory");
        __syncthreads();
        if (s + 2 < NST) load_stage((s + 2) % 3, (s + 2) * KC);

        const uint32_t Abu = sb + (uint32_t)(s % 3) * (BUF_FLOATS * 4);
        const uint32_t Bbu = Abu + KC * 128 * 4;

#pragma unroll
        for (int k = 0; k < KC; k++) {
            const uint32_t aa = Abu + (uint32_t)(k * 128 + mo) * 4;
            const uint32_t ba = Bbu + (uint32_t)(k * 128 + no) * 4;
            float af[8];
            unsigned long long bd[4];
            asm volatile("ld.shared.v4.f32 {%0,%1,%2,%3}, [%4];"
                         : "=f"(af[0]), "=f"(af[1]), "=f"(af[2]), "=f"(af[3]) : "r"(aa));
            asm volatile("ld.shared.v4.f32 {%0,%1,%2,%3}, [%4];"
                         : "=f"(af[4]), "=f"(af[5]), "=f"(af[6]), "=f"(af[7]) : "r"(aa + 16));
            asm volatile("ld.shared.v2.u64 {%0,%1}, [%2];"
                         : "=l"(bd[0]), "=l"(bd[1]) : "r"(ba));
            asm volatile("ld.shared.v2.u64 {%0,%1}, [%2];"
                         : "=l"(bd[2]), "=l"(bd[3]) : "r"(ba + 16));
            unsigned long long ad[8];
#pragma unroll
            for (int i = 0; i < 8; i++) PACK2(ad[i], af[i]);
#pragma unroll
            for (int i = 0; i < 8; i++)
#pragma unroll
                for (int j = 0; j < 4; j++)
                    FMA2(acc[i][j], ad[i], bd[j]);
        }
    }

    // epilogue: unpack, add bias, streaming store
    const int col = n0 + no;
    const float4 bb0 = *(const float4*)&bias[col];
    const float4 bb1 = *(const float4*)&bias[col + 4];
#pragma unroll
    for (int i = 0; i < 8; i++) {
        float v[8];
        UNPK2(v[0], v[1], acc[i][0]);
        UNPK2(v[2], v[3], acc[i][1]);
        UNPK2(v[4], v[5], acc[i][2]);
        UNPK2(v[6], v[7], acc[i][3]);
        float* dst = g_hall + (size_t)(m0 + mo + i) * H_ + col;
        float4 o0, o1;
        o0.x = v[0] + bb0.x; o0.y = v[1] + bb0.y;
        o0.z = v[2] + bb0.z; o0.w = v[3] + bb0.w;
        o1.x = v[4] + bb1.x; o1.y = v[5] + bb1.y;
        o1.z = v[6] + bb1.z; o1.w = v[7] + bb1.w;
        __stwt((float4*)(dst), o0);
        __stwt((float4*)(dst + 4), o1);
    }
}

// ---------------- Phase 2: sequential LIF scan ----------------
__global__ void __launch_bounds__(256) scan_kernel()
{
    const int idx = blockIdx.x * blockDim.x + threadIdx.x;
    const int flat = idx * 4;
    const float* p = g_hall + (size_t)flat;

    float v0 = 0.f, v1 = 0.f, v2 = 0.f, v3 = 0.f;
    float z0 = 0.f, z1 = 0.f, z2 = 0.f, z3 = 0.f;

#pragma unroll 4
    for (int t = 0; t < T_; t++) {
        const float4 hv = __ldcs((const float4*)(p + (size_t)t * ((size_t)B_ * H_)));
        v0 = 0.9f * v0 + hv.x; z0 = (v0 > 1.0f) ? 1.0f : 0.0f; v0 -= z0;
        v1 = 0.9f * v1 + hv.y; z1 = (v1 > 1.0f) ? 1.0f : 0.0f; v1 -= z1;
        v2 = 0.9f * v2 + hv.z; z2 = (v2 > 1.0f) ? 1.0f : 0.0f; v2 -= z2;
        v3 = 0.9f * v3 + hv.w; z3 = (v3 > 1.0f) ? 1.0f : 0.0f; v3 -= z3;
    }
    *(float4*)&g_z[flat] = make_float4(z0, z1, z2, z3);
}

// ---------------- Phase 3: classifier ----------------
__global__ void __launch_bounds__(256) cls_kernel(const float* __restrict__ Wout,
                                                  const float* __restrict__ bout,
                                                  float* __restrict__ out)
{
    const int gw = (blockIdx.x * blockDim.x + threadIdx.x) >> 5;
    const int lane = threadIdx.x & 31;
    if (gw >= B_ * C_) return;
    const int b = gw / C_;
    const int c = gw % C_;

    const float* zp = g_z + (size_t)b * H_;
    const float* wp = Wout + (size_t)c * H_;

    float s = 0.0f;
#pragma unroll
    for (int h = lane * 4; h < H_; h += 32 * 4) {
        const float4 zz = *(const float4*)&zp[h];
        const float4 ww = *(const float4*)&wp[h];
        s = fmaf(zz.x, ww.x, s);
        s = fmaf(zz.y, ww.y, s);
        s = fmaf(zz.z, ww.z, s);
        s = fmaf(zz.w, ww.w, s);
    }
#pragma unroll
    for (int o = 16; o > 0; o >>= 1)
        s += __shfl_xor_sync(0xffffffffu, s, o);
    if (lane == 0) out[(size_t)b * C_ + c] = s + bout[c];
}

// ---------------------------------------------------------------------------
extern "C" void kernel_launch(void* const* d_in, const int* in_sizes, int n_in,
                              void* d_out, int out_size)
{
    const float* x     = (const float*)d_in[0];  // [T, B, D] = [M, D]
    const float* W_in  = (const float*)d_in[1];  // [H, D]
    const float* b_in  = (const float*)d_in[2];  // [H]
    const float* W_out = (const float*)d_in[3];  // [C, H]
    const float* b_out = (const float*)d_in[4];  // [C]
    float* out = (float*)d_out;                  // [B, C]

    cudaFuncSetAttribute(gemm_kernel, cudaFuncAttributeMaxDynamicSharedMemorySize, SMEM_BYTES);

    void *pAt, *pWt;
    cudaGetSymbolAddress(&pAt, g_At);
    cudaGetSymbolAddress(&pWt, g_Wt);

    dim3 tb(32, 8);
    transpose_kernel<<<dim3(D_ / 32, M_ / 32), tb>>>(x, (float*)pAt, M_, D_);
    transpose_kernel<<<dim3(D_ / 32, H_ / 32), tb>>>(W_in, (float*)pWt, H_, D_);

    dim3 g(H_ / 128, M_ / 128);                  // 16 x 512 CTAs
    gemm_kernel<<<g, 256, SMEM_BYTES>>>(b_in);

    scan_kernel<<<(B_ * H_ / 4) / 256, 256>>>();

    cls_kernel<<<(B_ * C_ * 32) / 256, 256>>>(W_out, b_out, out);
}